// round 12
// baseline (speedup 1.0000x reference)
#include <cuda_runtime.h>
#include <cuda_fp16.h>
#include <cstdint>

// Seq2Seq GRU with HMMA (mma.sync m16n8k16 fp16->fp32), fp32-faithful via
// 2-limb fp16 decomposition x = h0 + h1; 3 limb products (A0B0+A1B0+A0B1).
// R12: 4 warps x (M64 x N48) warp tiles (was 8 x M32), 256 regs/thread,
//      software-pipelined A fragments across ks. CTA tile/grid/SMEM unchanged.

static const int B_ = 512;
static const int S_ = 64;
static const int T_ = 32;
static const int E_ = 512;
static const int H1 = 1024;
static const int H2 = 2048;
static const int V_ = 128;

// stage layout (bytes): A0 @ 0 (16K), A1 @ 16K, B0 @ 32K (12K), B1 @ 44K; 56K total
static const int STG_BYTES = 57344;
static const int OFF_A1 = 16384;
static const int OFF_B0 = 32768;
static const int OFF_B1 = 45056;

// ---------------- device scratch ----------------
__device__ float g_proj_f[V_ * 3 * H1];
__device__ float g_proj_b[V_ * 3 * H1];
__device__ float g_proj_d[V_ * 3 * H2];
__device__ float g_hf[2][B_ * H1];
__device__ float g_hb[2][B_ * H1];
__device__ float g_hh[2][B_ * H2];
__device__ uint4 g_hf_l0[2][B_ * H1 / 8];
__device__ uint4 g_hf_l1[2][B_ * H1 / 8];
__device__ uint4 g_hb_l0[2][B_ * H1 / 8];
__device__ uint4 g_hb_l1[2][B_ * H1 / 8];
__device__ uint4 g_hh_l0[2][B_ * H2 / 8];
__device__ uint4 g_hh_l1[2][B_ * H2 / 8];
__device__ uint4 g_Wf_l0[3 * H1 * H1 / 8];
__device__ uint4 g_Wf_l1[3 * H1 * H1 / 8];
__device__ uint4 g_Wb_l0[3 * H1 * H1 / 8];
__device__ uint4 g_Wb_l1[3 * H1 * H1 / 8];
__device__ uint4 g_Wd_l0[3 * H2 * H2 / 8];
__device__ uint4 g_Wd_l1[3 * H2 * H2 / 8];
__device__ float g_part[8][B_ * V_];
__device__ int   g_tok[B_];

__device__ __forceinline__ float sigmoid_(float x) { return 1.f / (1.f + __expf(-x)); }
__device__ __forceinline__ float tanh_(float x) {
    float e = __expf(2.f * x);
    return 1.f - 2.f / (e + 1.f);
}

#define SWZ(o) ((o) ^ (((o) >> 3) & 0x70))

__device__ __forceinline__ uint32_t smem_u32(const void* p) {
    uint32_t a;
    asm("{ .reg .u64 t; cvta.to.shared.u64 t, %1; cvt.u32.u64 %0, t; }" : "=r"(a) : "l"(p));
    return a;
}
__device__ __forceinline__ void split2h(float x, __half& a0, __half& a1) {
    a0 = __float2half_rn(x);
    a1 = __float2half_rn(x - __half2float(a0));
}
__device__ __forceinline__ void cp16(uint32_t dst, const void* src) {
    asm volatile("cp.async.cg.shared.global [%0], [%1], 16;" :: "r"(dst), "l"(src));
}
__device__ __forceinline__ void cp_commit() {
    asm volatile("cp.async.commit_group;" ::: "memory");
}
template<int N>
__device__ __forceinline__ void cp_wait() {
    asm volatile("cp.async.wait_group %0;" :: "n"(N) : "memory");
}
#define LDSM_X4(r0, r1, r2, r3, addr) \
    asm volatile("ldmatrix.sync.aligned.m8n8.x4.shared.b16 {%0,%1,%2,%3}, [%4];" \
                 : "=r"(r0), "=r"(r1), "=r"(r2), "=r"(r3) : "r"(addr))
#define MMA16816(acc, af, b0, b1) \
    asm volatile("mma.sync.aligned.m16n8k16.row.col.f32.f16.f16.f32 " \
                 "{%0,%1,%2,%3}, {%4,%5,%6,%7}, {%8,%9}, {%0,%1,%2,%3};" \
                 : "+f"((acc)[0]), "+f"((acc)[1]), "+f"((acc)[2]), "+f"((acc)[3]) \
                 : "r"((af)[0]), "r"((af)[1]), "r"((af)[2]), "r"((af)[3]), \
                   "r"(b0), "r"(b1))

// ---------------- fused prep: limb-split all weights + zero encoder h ----------------
static const int NF = 3 * H1 * H1;
static const int ND = 3 * H2 * H2;
__global__ void split_all_kernel(const float* __restrict__ Wf,
                                 const float* __restrict__ Wb,
                                 const float* __restrict__ Wd)
{
    long long i = (long long)blockIdx.x * blockDim.x + threadIdx.x;
    if (i < B_ * H1) { g_hf[0][i] = 0.f; g_hb[0][i] = 0.f; }
    if (i < B_ * H1 / 8) {
        uint4 z = make_uint4(0, 0, 0, 0);
        g_hf_l0[0][i] = z; g_hf_l1[0][i] = z;
        g_hb_l0[0][i] = z; g_hb_l1[0][i] = z;
    }
    const float* src; __half *o0, *o1; long long k;
    if (i < NF)                 { src = Wf; k = i;            o0 = (__half*)g_Wf_l0; o1 = (__half*)g_Wf_l1; }
    else if (i < 2LL * NF)      { src = Wb; k = i - NF;       o0 = (__half*)g_Wb_l0; o1 = (__half*)g_Wb_l1; }
    else if (i < 2LL * NF + ND) { src = Wd; k = i - 2LL * NF; o0 = (__half*)g_Wd_l0; o1 = (__half*)g_Wd_l1; }
    else return;
    __half a0, a1;
    split2h(src[k], a0, a1);
    o0[k] = a0; o1[k] = a1;
}

// ---------------- fused projection tables: out[128][N] = Emb @ W^T + b ----------------
__global__ __launch_bounds__(256)
void proj_all_kernel(const float* __restrict__ enc_emb, const float* __restrict__ dec_emb,
                     const float* __restrict__ Wf, const float* __restrict__ Wb,
                     const float* __restrict__ Wd,
                     const float* __restrict__ bf, const float* __restrict__ bb,
                     const float* __restrict__ bd)
{
    const int which = blockIdx.z;
    const int N = (which == 2) ? 3 * H2 : 3 * H1;
    if (blockIdx.x * 64 >= N) return;
    const float* Emb = (which == 2) ? dec_emb : enc_emb;
    const float* W   = (which == 0) ? Wf : (which == 1) ? Wb : Wd;
    const float* b   = (which == 0) ? bf : (which == 1) ? bb : bd;
    float* out = (which == 0) ? g_proj_f : (which == 1) ? g_proj_b : g_proj_d;

    const int n0 = blockIdx.x * 64, m0 = blockIdx.y * 64;
    const int tid = threadIdx.x;
    const int tx = tid & 15, ty = tid >> 4;

    __shared__ float sA[32][64];
    __shared__ float sB[32][64];

    float acc[4][4];
    #pragma unroll
    for (int i = 0; i < 4; i++)
        #pragma unroll
        for (int j = 0; j < 4; j++) acc[i][j] = 0.f;

    for (int k0 = 0; k0 < E_; k0 += 32) {
        #pragma unroll
        for (int it = 0; it < 2; ++it) {
            int idx = tid + it * 256;
            int r = idx >> 3, k4 = (idx & 7) * 4;
            float4 v = *(const float4*)&Emb[(m0 + r) * E_ + k0 + k4];
            sA[k4 + 0][r] = v.x; sA[k4 + 1][r] = v.y;
            sA[k4 + 2][r] = v.z; sA[k4 + 3][r] = v.w;
        }
        #pragma unroll
        for (int it = 0; it < 2; ++it) {
            int idx = tid + it * 256;
            int r = idx >> 3, k4 = (idx & 7) * 4;
            float4 v = *(const float4*)&W[(n0 + r) * E_ + k0 + k4];
            sB[k4 + 0][r] = v.x; sB[k4 + 1][r] = v.y;
            sB[k4 + 2][r] = v.z; sB[k4 + 3][r] = v.w;
        }
        __syncthreads();
        #pragma unroll
        for (int kk = 0; kk < 32; ++kk) {
            float4 a4 = *(const float4*)&sA[kk][ty * 4];
            float4 b4 = *(const float4*)&sB[kk][tx * 4];
            float a[4] = {a4.x, a4.y, a4.z, a4.w};
            float w[4] = {b4.x, b4.y, b4.z, b4.w};
            #pragma unroll
            for (int i = 0; i < 4; i++)
                #pragma unroll
                for (int j = 0; j < 4; j++)
                    acc[i][j] = fmaf(a[i], w[j], acc[i][j]);
        }
        __syncthreads();
    }

    #pragma unroll
    for (int i = 0; i < 4; i++) {
        int m = m0 + ty * 4 + i;
        #pragma unroll
        for (int j = 0; j < 4; j++) {
            int n = n0 + tx * 4 + j;
            out[m * N + n] = acc[i][j] + b[n];
        }
    }
}

// ---------------- HMMA GRU step: 4 warps x (M64 x N48), pipelined frags ----------------
// CTA: 128 batch (blockIdx.y) x 32 j (blockIdx.x) x 3 gates -> N=96.
// 2 stages x 56KB; epilogue reuses SMEM as fp32 C [128][100].
template<int HH>
__global__ __launch_bounds__(128, 2)
void gru_step_mma(const int* __restrict__ toks, const float* __restrict__ bhh_a,
                  const float* __restrict__ bhh_b, int pp, int s)
{
    extern __shared__ char smem[];
    const uint32_t su = smem_u32(smem);
    const int tid = threadIdx.x;

    const uint4 *w0, *w1, *h0p, *h1p;
    uint4 *hn0, *hn1;
    const float *hold, *bhh, *proj;
    float* hnew;
    int t = 0;
    if (HH == H1) {
        const int dir = blockIdx.z;
        if (dir == 0) {
            w0 = g_Wf_l0; w1 = g_Wf_l1;
            h0p = g_hf_l0[pp]; h1p = g_hf_l1[pp];
            hn0 = g_hf_l0[pp ^ 1]; hn1 = g_hf_l1[pp ^ 1];
            hold = g_hf[pp]; hnew = g_hf[pp ^ 1];
            bhh = bhh_a; proj = g_proj_f; t = s;
        } else {
            w0 = g_Wb_l0; w1 = g_Wb_l1;
            h0p = g_hb_l0[pp]; h1p = g_hb_l1[pp];
            hn0 = g_hb_l0[pp ^ 1]; hn1 = g_hb_l1[pp ^ 1];
            hold = g_hb[pp]; hnew = g_hb[pp ^ 1];
            bhh = bhh_b; proj = g_proj_b; t = S_ - 1 - s;
        }
    } else {
        w0 = g_Wd_l0; w1 = g_Wd_l1;
        h0p = g_hh_l0[pp]; h1p = g_hh_l1[pp];
        hn0 = g_hh_l0[pp ^ 1]; hn1 = g_hh_l1[pp ^ 1];
        hold = g_hh[pp]; hnew = g_hh[pp ^ 1];
        bhh = bhh_a; proj = g_proj_d;
    }

    const int m0 = blockIdx.y * 128;
    const int j0 = blockIdx.x * 32;

    const int w = tid >> 5, lane = tid & 31;
    const int wm = w >> 1, wn = w & 1;       // 2 x 2 warp grid: M=64, N=48 per warp

    float acc[4][6][4];
    #pragma unroll
    for (int mi = 0; mi < 4; ++mi)
        #pragma unroll
        for (int ni = 0; ni < 6; ++ni)
            #pragma unroll
            for (int q = 0; q < 4; ++q) acc[mi][ni][q] = 0.f;

    const int NCH = HH / 64;

    auto stage_load = [&](int c, int st) {
        const int k0 = c * 64;
        const uint32_t sb = su + st * STG_BYTES;
        #pragma unroll
        for (int it = 0; it < 8; ++it) {
            int idx = tid + it * 128;
            int r = idx >> 3, kb = idx & 7;
            int gi = ((m0 + r) * HH + k0) / 8 + kb;
            uint32_t o = SWZ((uint32_t)(r * 128 + kb * 16));
            cp16(sb + o, &h0p[gi]);
            cp16(sb + OFF_A1 + o, &h1p[gi]);
        }
        #pragma unroll
        for (int it = 0; it < 6; ++it) {
            int idx = tid + it * 128;
            int rsm = idx >> 3, kb = idx & 7;
            int g = rsm >> 5, jl = rsm & 31;
            int gi = ((g * HH + j0 + jl) * HH + k0) / 8 + kb;
            uint32_t o = SWZ((uint32_t)(rsm * 128 + kb * 16));
            cp16(sb + OFF_B0 + o, &w0[gi]);
            cp16(sb + OFF_B1 + o, &w1[gi]);
        }
    };

    stage_load(0, 0);
    cp_commit();

    // B ldmatrix.x4 lane mapping: quads 0,1 -> limb0 (k lo/hi 16B); quads 2,3 -> limb1
    const int bquad = lane >> 3;
    const uint32_t blimb_off = (bquad >= 2) ? (uint32_t)OFF_B1 : (uint32_t)OFF_B0;
    const uint32_t bk_off = (uint32_t)(bquad & 1) * 16;
    const int bn_lane = lane & 7;
    // A ldmatrix address pieces
    const int arow_l = lane & 15;
    const uint32_t acol16 = (uint32_t)((lane >> 4) << 4);

    for (int c = 0; c < NCH; ++c) {
        if (c + 1 < NCH) {
            stage_load(c + 1, (c + 1) & 1);
            cp_commit();
            cp_wait<1>();
        } else {
            cp_wait<0>();
        }
        __syncthreads();

        const uint32_t sb = su + (c & 1) * STG_BYTES;

        // software-pipelined A fragments: [buf][limb][mi][4]
        uint32_t af[2][2][4][4];
        auto load_a = [&](int ks, int buf) {
            #pragma unroll
            for (int mi = 0; mi < 4; ++mi) {
                int row = wm * 64 + mi * 16 + arow_l;
                uint32_t o = SWZ((uint32_t)(row * 128 + ks * 32 + acol16));
                LDSM_X4(af[buf][0][mi][0], af[buf][0][mi][1],
                        af[buf][0][mi][2], af[buf][0][mi][3], sb + o);
                LDSM_X4(af[buf][1][mi][0], af[buf][1][mi][1],
                        af[buf][1][mi][2], af[buf][1][mi][3], sb + OFF_A1 + o);
            }
        };

        load_a(0, 0);
        #pragma unroll
        for (int ks = 0; ks < 4; ++ks) {
            const int buf = ks & 1;
            if (ks < 3) load_a(ks + 1, buf ^ 1);
            #pragma unroll
            for (int ni = 0; ni < 6; ++ni) {
                int nrow = wn * 48 + ni * 8 + bn_lane;
                uint32_t baddr = sb + blimb_off
                               + SWZ((uint32_t)(nrow * 128 + ks * 32 + bk_off));
                uint32_t b00, b01, b10, b11;
                LDSM_X4(b00, b01, b10, b11, baddr);
                #pragma unroll
                for (int mi = 0; mi < 4; ++mi) {
                    MMA16816(acc[mi][ni], af[buf][0][mi], b00, b01);   // A0*B0
                    MMA16816(acc[mi][ni], af[buf][1][mi], b00, b01);   // A1*B0
                    MMA16816(acc[mi][ni], af[buf][0][mi], b10, b11);   // A0*B1
                }
            }
        }
        __syncthreads();
    }

    // ---- epilogue: C -> SMEM roundtrip (co-locate r/z/n), then gate math ----
    float* sC = (float*)smem;   // [128][100]
    #pragma unroll
    for (int mi = 0; mi < 4; ++mi)
        #pragma unroll
        for (int ni = 0; ni < 6; ++ni) {
            int row = wm * 64 + mi * 16 + (lane >> 2);
            int col = wn * 48 + ni * 8 + 2 * (lane & 3);
            sC[row * 100 + col]           = acc[mi][ni][0];
            sC[row * 100 + col + 1]       = acc[mi][ni][1];
            sC[(row + 8) * 100 + col]     = acc[mi][ni][2];
            sC[(row + 8) * 100 + col + 1] = acc[mi][ni][3];
        }
    __syncthreads();

    {
        const int m_l = tid;               // one row per thread (128 rows)
        const int mg = m0 + m_l;
        const int token = (HH == H1) ? toks[mg * S_ + t] : g_tok[mg];
        const float* pr = &proj[token * (3 * HH)];
        __half* ph0 = (__half*)hn0;
        __half* ph1 = (__half*)hn1;
        #pragma unroll
        for (int jl = 0; jl < 32; ++jl) {
            int jj = j0 + jl;
            float h_r = sC[m_l * 100 + jl]      + bhh[jj];
            float h_z = sC[m_l * 100 + 32 + jl] + bhh[HH + jj];
            float h_n = sC[m_l * 100 + 64 + jl] + bhh[2 * HH + jj];
            float r = sigmoid_(pr[jj] + h_r);
            float z = sigmoid_(pr[HH + jj] + h_z);
            float n = tanh_(pr[2 * HH + jj] + r * h_n);
            float ho = hold[mg * HH + jj];
            float hv = (1.f - z) * n + z * ho;
            hnew[mg * HH + jj] = hv;
            __half a0h, a1h;
            split2h(hv, a0h, a1h);
            ph0[mg * HH + jj] = a0h;
            ph1[mg * HH + jj] = a1h;
        }
    }
}

// ---------------- logits: split-K partial GEMM + reduce/argmax ----------------
__global__ __launch_bounds__(256)
void logits_partial_kernel(const float* __restrict__ Wfc, int pp)
{
    const float* hh = g_hh[pp ^ 1];
    const int b0 = blockIdx.x * 32;
    const int ks = blockIdx.y * 256;
    const int tid = threadIdx.x;
    const int tx = tid & 31, ty = tid >> 5;

    __shared__ float sA[32][32];
    __shared__ float sB[32][128];

    float acc[4][4];
    #pragma unroll
    for (int i = 0; i < 4; i++)
        #pragma unroll
        for (int j = 0; j < 4; j++) acc[i][j] = 0.f;

    for (int k0 = ks; k0 < ks + 256; k0 += 32) {
        {
            int r = tid >> 3, k4 = (tid & 7) * 4;
            float4 v = *(const float4*)&hh[(b0 + r) * H2 + k0 + k4];
            sA[k4 + 0][r] = v.x; sA[k4 + 1][r] = v.y;
            sA[k4 + 2][r] = v.z; sA[k4 + 3][r] = v.w;
        }
        #pragma unroll
        for (int it = 0; it < 4; ++it) {
            int idx = tid + it * 256;
            int r = idx >> 3, k4 = (idx & 7) * 4;
            float4 v = *(const float4*)&Wfc[r * H2 + k0 + k4];
            sB[k4 + 0][r] = v.x; sB[k4 + 1][r] = v.y;
            sB[k4 + 2][r] = v.z; sB[k4 + 3][r] = v.w;
        }
        __syncthreads();
        #pragma unroll
        for (int kk = 0; kk < 32; ++kk) {
            float4 a4 = *(const float4*)&sA[kk][ty * 4];
            float4 b4 = *(const float4*)&sB[kk][tx * 4];
            float a[4] = {a4.x, a4.y, a4.z, a4.w};
            float wv[4] = {b4.x, b4.y, b4.z, b4.w};
            #pragma unroll
            for (int i = 0; i < 4; i++)
                #pragma unroll
                for (int j = 0; j < 4; j++)
                    acc[i][j] = fmaf(a[i], wv[j], acc[i][j]);
        }
        __syncthreads();
    }

    #pragma unroll
    for (int i = 0; i < 4; i++)
        #pragma unroll
        for (int j = 0; j < 4; j++)
            g_part[blockIdx.y][(b0 + ty * 4 + i) * V_ + tx * 4 + j] = acc[i][j];
}

__global__ void logits_reduce_kernel(const float* __restrict__ bfc,
                                     float* __restrict__ out, int t)
{
    const int b = blockIdx.x;
    const int v = threadIdx.x;
    float s = bfc[v];
    #pragma unroll
    for (int p = 0; p < 8; p++) s += g_part[p][b * V_ + v];
    out[(b * (T_ - 1) + t) * V_ + v] = s;

    __shared__ float sv[V_];
    __shared__ int   si[V_];
    sv[v] = s; si[v] = v;
    __syncthreads();
    for (int off = 64; off > 0; off >>= 1) {
        if (v < off) {
            float o = sv[v + off]; int oi = si[v + off];
            if (o > sv[v] || (o == sv[v] && oi < si[v])) { sv[v] = o; si[v] = oi; }
        }
        __syncthreads();
    }
    if (v == 0) g_tok[b] = si[0];
}

// ---------------- init decoder ----------------
__global__ void init_dec_kernel(const int* __restrict__ tgt)
{
    int i = blockIdx.x * blockDim.x + threadIdx.x;
    if (i < B_ * H2) {
        int b = i >> 11, j = i & (H2 - 1);
        float v = (j < H1) ? g_hf[0][b * H1 + j] : g_hb[0][b * H1 + (j - H1)];
        g_hh[0][i] = v;
        __half a0, a1;
        split2h(v, a0, a1);
        ((__half*)g_hh_l0[0])[i] = a0;
        ((__half*)g_hh_l1[0])[i] = a1;
    }
    if (i < B_) g_tok[i] = tgt[i * T_];
}

// ---------------- launch ----------------
extern "C" void kernel_launch(void* const* d_in, const int* in_sizes, int n_in,
                              void* d_out, int out_size)
{
    const int*   src     = (const int*)d_in[0];
    const int*   tgt     = (const int*)d_in[1];
    const float* enc_emb = (const float*)d_in[2];
    const float* dec_emb = (const float*)d_in[3];
    const float* W_ih_f  = (const float*)d_in[4];
    const float* W_hh_f  = (const float*)d_in[5];
    const float* b_ih_f  = (const float*)d_in[6];
    const float* b_hh_f  = (const float*)d_in[7];
    const float* W_ih_b  = (const float*)d_in[8];
    const float* W_hh_b  = (const float*)d_in[9];
    const float* b_ih_b  = (const float*)d_in[10];
    const float* b_hh_b  = (const float*)d_in[11];
    const float* W_ih_d  = (const float*)d_in[12];
    const float* W_hh_d  = (const float*)d_in[13];
    const float* b_ih_d  = (const float*)d_in[14];
    const float* b_hh_d  = (const float*)d_in[15];
    const float* W_fc    = (const float*)d_in[16];
    const float* b_fc    = (const float*)d_in[17];
    float* out = (float*)d_out;

    const int SMEM = 2 * STG_BYTES;   // 112KB
    cudaFuncSetAttribute(gru_step_mma<H1>,
        cudaFuncAttributeMaxDynamicSharedMemorySize, SMEM);
    cudaFuncSetAttribute(gru_step_mma<H2>,
        cudaFuncAttributeMaxDynamicSharedMemorySize, SMEM);

    // prep (2 launches): proj tables, then weight limb-split + encoder h zero
    proj_all_kernel<<<dim3(3 * H2 / 64, 2, 3), 256>>>(
        enc_emb, dec_emb, W_ih_f, W_ih_b, W_ih_d, b_ih_f, b_ih_b, b_ih_d);
    {
        long long total = 2LL * NF + ND;
        split_all_kernel<<<(unsigned)((total + 255) / 256), 256>>>(W_hh_f, W_hh_b, W_hh_d);
    }

    for (int s = 0; s < S_; s++)
        gru_step_mma<H1><<<dim3(H1 / 32, B_ / 128, 2), 128, SMEM>>>(
            src, b_hh_f, b_hh_b, s & 1, s);
    // s=63: pp=1 -> writes buffer 0; final encoder state in buffer 0

    init_dec_kernel<<<(B_ * H2 + 255) / 256, 256>>>(tgt);

    for (int t = 0; t < T_ - 1; t++) {
        gru_step_mma<H2><<<dim3(H2 / 32, B_ / 128, 1), 128, SMEM>>>(
            (const int*)nullptr, b_hh_d, b_hh_d, t & 1, 0);
        logits_partial_kernel<<<dim3(B_ / 32, 8), 256>>>(W_fc, t & 1);
        logits_reduce_kernel<<<B_, V_>>>(b_fc, out, t);
    }
}

// round 15
// speedup vs baseline: 1.1496x; 1.1496x over previous
#include <cuda_runtime.h>
#include <cuda_fp16.h>
#include <cstdint>

// Seq2Seq GRU with HMMA (mma.sync m16n8k16 fp16->fp32), fp32-faithful via
// 2-limb fp16 decomposition x = h0 + h1; 3 limb products (A0B0+A1B0+A0B1).
// R13: revert to R11 shape (8 warps x M32xN48, 256 thr, 2 CTA/SM); batch all
//      10 ldmatrix per ks-slice up front (1 stall/ks instead of 6), then 36 MMA.

static const int B_ = 512;
static const int S_ = 64;
static const int T_ = 32;
static const int E_ = 512;
static const int H1 = 1024;
static const int H2 = 2048;
static const int V_ = 128;

// stage layout (bytes): A0 @ 0 (16K), A1 @ 16K, B0 @ 32K (12K), B1 @ 44K; 56K total
static const int STG_BYTES = 57344;
static const int OFF_A1 = 16384;
static const int OFF_B0 = 32768;
static const int OFF_B1 = 45056;

// ---------------- device scratch ----------------
__device__ float g_proj_f[V_ * 3 * H1];
__device__ float g_proj_b[V_ * 3 * H1];
__device__ float g_proj_d[V_ * 3 * H2];
__device__ float g_hf[2][B_ * H1];
__device__ float g_hb[2][B_ * H1];
__device__ float g_hh[2][B_ * H2];
__device__ uint4 g_hf_l0[2][B_ * H1 / 8];
__device__ uint4 g_hf_l1[2][B_ * H1 / 8];
__device__ uint4 g_hb_l0[2][B_ * H1 / 8];
__device__ uint4 g_hb_l1[2][B_ * H1 / 8];
__device__ uint4 g_hh_l0[2][B_ * H2 / 8];
__device__ uint4 g_hh_l1[2][B_ * H2 / 8];
__device__ uint4 g_Wf_l0[3 * H1 * H1 / 8];
__device__ uint4 g_Wf_l1[3 * H1 * H1 / 8];
__device__ uint4 g_Wb_l0[3 * H1 * H1 / 8];
__device__ uint4 g_Wb_l1[3 * H1 * H1 / 8];
__device__ uint4 g_Wd_l0[3 * H2 * H2 / 8];
__device__ uint4 g_Wd_l1[3 * H2 * H2 / 8];
__device__ float g_part[8][B_ * V_];
__device__ int   g_tok[B_];

__device__ __forceinline__ float sigmoid_(float x) { return 1.f / (1.f + __expf(-x)); }
__device__ __forceinline__ float tanh_(float x) {
    float e = __expf(2.f * x);
    return 1.f - 2.f / (e + 1.f);
}

#define SWZ(o) ((o) ^ (((o) >> 3) & 0x70))

__device__ __forceinline__ uint32_t smem_u32(const void* p) {
    uint32_t a;
    asm("{ .reg .u64 t; cvta.to.shared.u64 t, %1; cvt.u32.u64 %0, t; }" : "=r"(a) : "l"(p));
    return a;
}
__device__ __forceinline__ void split2h(float x, __half& a0, __half& a1) {
    a0 = __float2half_rn(x);
    a1 = __float2half_rn(x - __half2float(a0));
}
__device__ __forceinline__ void cp16(uint32_t dst, const void* src) {
    asm volatile("cp.async.cg.shared.global [%0], [%1], 16;" :: "r"(dst), "l"(src));
}
__device__ __forceinline__ void cp_commit() {
    asm volatile("cp.async.commit_group;" ::: "memory");
}
template<int N>
__device__ __forceinline__ void cp_wait() {
    asm volatile("cp.async.wait_group %0;" :: "n"(N) : "memory");
}
#define LDSM_X4(r0, r1, r2, r3, addr) \
    asm volatile("ldmatrix.sync.aligned.m8n8.x4.shared.b16 {%0,%1,%2,%3}, [%4];" \
                 : "=r"(r0), "=r"(r1), "=r"(r2), "=r"(r3) : "r"(addr))
#define MMA16816(acc, af, b0, b1) \
    asm volatile("mma.sync.aligned.m16n8k16.row.col.f32.f16.f16.f32 " \
                 "{%0,%1,%2,%3}, {%4,%5,%6,%7}, {%8,%9}, {%0,%1,%2,%3};" \
                 : "+f"((acc)[0]), "+f"((acc)[1]), "+f"((acc)[2]), "+f"((acc)[3]) \
                 : "r"((af)[0]), "r"((af)[1]), "r"((af)[2]), "r"((af)[3]), \
                   "r"(b0), "r"(b1))

// ---------------- fused prep: limb-split all weights + zero encoder h ----------------
static const int NF = 3 * H1 * H1;
static const int ND = 3 * H2 * H2;
__global__ void split_all_kernel(const float* __restrict__ Wf,
                                 const float* __restrict__ Wb,
                                 const float* __restrict__ Wd)
{
    long long i = (long long)blockIdx.x * blockDim.x + threadIdx.x;
    if (i < B_ * H1) { g_hf[0][i] = 0.f; g_hb[0][i] = 0.f; }
    if (i < B_ * H1 / 8) {
        uint4 z = make_uint4(0, 0, 0, 0);
        g_hf_l0[0][i] = z; g_hf_l1[0][i] = z;
        g_hb_l0[0][i] = z; g_hb_l1[0][i] = z;
    }
    const float* src; __half *o0, *o1; long long k;
    if (i < NF)                 { src = Wf; k = i;            o0 = (__half*)g_Wf_l0; o1 = (__half*)g_Wf_l1; }
    else if (i < 2LL * NF)      { src = Wb; k = i - NF;       o0 = (__half*)g_Wb_l0; o1 = (__half*)g_Wb_l1; }
    else if (i < 2LL * NF + ND) { src = Wd; k = i - 2LL * NF; o0 = (__half*)g_Wd_l0; o1 = (__half*)g_Wd_l1; }
    else return;
    __half a0, a1;
    split2h(src[k], a0, a1);
    o0[k] = a0; o1[k] = a1;
}

// ---------------- fused projection tables: out[128][N] = Emb @ W^T + b ----------------
__global__ __launch_bounds__(256)
void proj_all_kernel(const float* __restrict__ enc_emb, const float* __restrict__ dec_emb,
                     const float* __restrict__ Wf, const float* __restrict__ Wb,
                     const float* __restrict__ Wd,
                     const float* __restrict__ bf, const float* __restrict__ bb,
                     const float* __restrict__ bd)
{
    const int which = blockIdx.z;
    const int N = (which == 2) ? 3 * H2 : 3 * H1;
    if (blockIdx.x * 64 >= N) return;
    const float* Emb = (which == 2) ? dec_emb : enc_emb;
    const float* W   = (which == 0) ? Wf : (which == 1) ? Wb : Wd;
    const float* b   = (which == 0) ? bf : (which == 1) ? bb : bd;
    float* out = (which == 0) ? g_proj_f : (which == 1) ? g_proj_b : g_proj_d;

    const int n0 = blockIdx.x * 64, m0 = blockIdx.y * 64;
    const int tid = threadIdx.x;
    const int tx = tid & 15, ty = tid >> 4;

    __shared__ float sA[32][64];
    __shared__ float sB[32][64];

    float acc[4][4];
    #pragma unroll
    for (int i = 0; i < 4; i++)
        #pragma unroll
        for (int j = 0; j < 4; j++) acc[i][j] = 0.f;

    for (int k0 = 0; k0 < E_; k0 += 32) {
        #pragma unroll
        for (int it = 0; it < 2; ++it) {
            int idx = tid + it * 256;
            int r = idx >> 3, k4 = (idx & 7) * 4;
            float4 v = *(const float4*)&Emb[(m0 + r) * E_ + k0 + k4];
            sA[k4 + 0][r] = v.x; sA[k4 + 1][r] = v.y;
            sA[k4 + 2][r] = v.z; sA[k4 + 3][r] = v.w;
        }
        #pragma unroll
        for (int it = 0; it < 2; ++it) {
            int idx = tid + it * 256;
            int r = idx >> 3, k4 = (idx & 7) * 4;
            float4 v = *(const float4*)&W[(n0 + r) * E_ + k0 + k4];
            sB[k4 + 0][r] = v.x; sB[k4 + 1][r] = v.y;
            sB[k4 + 2][r] = v.z; sB[k4 + 3][r] = v.w;
        }
        __syncthreads();
        #pragma unroll
        for (int kk = 0; kk < 32; ++kk) {
            float4 a4 = *(const float4*)&sA[kk][ty * 4];
            float4 b4 = *(const float4*)&sB[kk][tx * 4];
            float a[4] = {a4.x, a4.y, a4.z, a4.w};
            float w[4] = {b4.x, b4.y, b4.z, b4.w};
            #pragma unroll
            for (int i = 0; i < 4; i++)
                #pragma unroll
                for (int j = 0; j < 4; j++)
                    acc[i][j] = fmaf(a[i], w[j], acc[i][j]);
        }
        __syncthreads();
    }

    #pragma unroll
    for (int i = 0; i < 4; i++) {
        int m = m0 + ty * 4 + i;
        #pragma unroll
        for (int j = 0; j < 4; j++) {
            int n = n0 + tx * 4 + j;
            out[m * N + n] = acc[i][j] + b[n];
        }
    }
}

// ---------------- HMMA GRU step: 8 warps x (M32 x N48), batched ldsm ----------------
// CTA: 128 batch (blockIdx.y) x 32 j (blockIdx.x) x 3 gates -> N=96.
// 2 stages x 56KB; epilogue reuses SMEM as fp32 C [128][100].
template<int HH>
__global__ __launch_bounds__(256, 2)
void gru_step_mma(const int* __restrict__ toks, const float* __restrict__ bhh_a,
                  const float* __restrict__ bhh_b, int pp, int s)
{
    extern __shared__ char smem[];
    const uint32_t su = smem_u32(smem);
    const int tid = threadIdx.x;

    const uint4 *w0, *w1, *h0p, *h1p;
    uint4 *hn0, *hn1;
    const float *hold, *bhh, *proj;
    float* hnew;
    int t = 0;
    if (HH == H1) {
        const int dir = blockIdx.z;
        if (dir == 0) {
            w0 = g_Wf_l0; w1 = g_Wf_l1;
            h0p = g_hf_l0[pp]; h1p = g_hf_l1[pp];
            hn0 = g_hf_l0[pp ^ 1]; hn1 = g_hf_l1[pp ^ 1];
            hold = g_hf[pp]; hnew = g_hf[pp ^ 1];
            bhh = bhh_a; proj = g_proj_f; t = s;
        } else {
            w0 = g_Wb_l0; w1 = g_Wb_l1;
            h0p = g_hb_l0[pp]; h1p = g_hb_l1[pp];
            hn0 = g_hb_l0[pp ^ 1]; hn1 = g_hb_l1[pp ^ 1];
            hold = g_hb[pp]; hnew = g_hb[pp ^ 1];
            bhh = bhh_b; proj = g_proj_b; t = S_ - 1 - s;
        }
    } else {
        w0 = g_Wd_l0; w1 = g_Wd_l1;
        h0p = g_hh_l0[pp]; h1p = g_hh_l1[pp];
        hn0 = g_hh_l0[pp ^ 1]; hn1 = g_hh_l1[pp ^ 1];
        hold = g_hh[pp]; hnew = g_hh[pp ^ 1];
        bhh = bhh_a; proj = g_proj_d;
    }

    const int m0 = blockIdx.y * 128;
    const int j0 = blockIdx.x * 32;

    const int w = tid >> 5, lane = tid & 31;
    const int wm = w >> 1, wn = w & 1;       // 4 x 2 warp grid: M=32, N=48 per warp

    float acc[2][6][4];
    #pragma unroll
    for (int mi = 0; mi < 2; ++mi)
        #pragma unroll
        for (int ni = 0; ni < 6; ++ni)
            #pragma unroll
            for (int q = 0; q < 4; ++q) acc[mi][ni][q] = 0.f;

    const int NCH = HH / 64;

    auto stage_load = [&](int c, int st) {
        const int k0 = c * 64;
        const uint32_t sb = su + st * STG_BYTES;
        #pragma unroll
        for (int it = 0; it < 4; ++it) {
            int idx = tid + it * 256;
            int r = idx >> 3, kb = idx & 7;
            int gi = ((m0 + r) * HH + k0) / 8 + kb;
            uint32_t o = SWZ((uint32_t)(r * 128 + kb * 16));
            cp16(sb + o, &h0p[gi]);
            cp16(sb + OFF_A1 + o, &h1p[gi]);
        }
        #pragma unroll
        for (int it = 0; it < 3; ++it) {
            int idx = tid + it * 256;
            int rsm = idx >> 3, kb = idx & 7;
            int g = rsm >> 5, jl = rsm & 31;
            int gi = ((g * HH + j0 + jl) * HH + k0) / 8 + kb;
            uint32_t o = SWZ((uint32_t)(rsm * 128 + kb * 16));
            cp16(sb + OFF_B0 + o, &w0[gi]);
            cp16(sb + OFF_B1 + o, &w1[gi]);
        }
    };

    stage_load(0, 0);
    cp_commit();

    // B ldmatrix.x4 lane mapping: quads 0,1 -> limb0 (k lo/hi 16B); quads 2,3 -> limb1
    const int bquad = lane >> 3;
    const uint32_t blimb_off = (bquad >= 2) ? (uint32_t)OFF_B1 : (uint32_t)OFF_B0;
    const uint32_t bk_off = (uint32_t)(bquad & 1) * 16;
    const int bn_lane = lane & 7;
    const int arow_l = lane & 15;
    const uint32_t acol16 = (uint32_t)((lane >> 4) << 4);

    for (int c = 0; c < NCH; ++c) {
        if (c + 1 < NCH) {
            stage_load(c + 1, (c + 1) & 1);
            cp_commit();
            cp_wait<1>();
        } else {
            cp_wait<0>();
        }
        __syncthreads();

        const uint32_t sb = su + (c & 1) * STG_BYTES;
        #pragma unroll
        for (int ks = 0; ks < 4; ++ks) {
            // ---- batch ALL loads for this ks: 4 A ldsm + 6 B ldsm in flight ----
            uint32_t a0[2][4], a1[2][4], bf[6][4];
            #pragma unroll
            for (int mi = 0; mi < 2; ++mi) {
                int row = wm * 32 + mi * 16 + arow_l;
                uint32_t o = SWZ((uint32_t)(row * 128 + ks * 32 + acol16));
                LDSM_X4(a0[mi][0], a0[mi][1], a0[mi][2], a0[mi][3], sb + o);
                LDSM_X4(a1[mi][0], a1[mi][1], a1[mi][2], a1[mi][3], sb + OFF_A1 + o);
            }
            #pragma unroll
            for (int ni = 0; ni < 6; ++ni) {
                int nrow = wn * 48 + ni * 8 + bn_lane;
                uint32_t baddr = sb + blimb_off
                               + SWZ((uint32_t)(nrow * 128 + ks * 32 + bk_off));
                LDSM_X4(bf[ni][0], bf[ni][1], bf[ni][2], bf[ni][3], baddr);
            }
            // ---- 36 MMA back-to-back ----
            #pragma unroll
            for (int ni = 0; ni < 6; ++ni)
                #pragma unroll
                for (int mi = 0; mi < 2; ++mi) {
                    MMA16816(acc[mi][ni], a0[mi], bf[ni][0], bf[ni][1]);   // A0*B0
                    MMA16816(acc[mi][ni], a1[mi], bf[ni][0], bf[ni][1]);   // A1*B0
                    MMA16816(acc[mi][ni], a0[mi], bf[ni][2], bf[ni][3]);   // A0*B1
                }
        }
        __syncthreads();
    }

    // ---- epilogue: C -> SMEM roundtrip (co-locate r/z/n), then gate math ----
    float* sC = (float*)smem;   // [128][100]
    #pragma unroll
    for (int mi = 0; mi < 2; ++mi)
        #pragma unroll
        for (int ni = 0; ni < 6; ++ni) {
            int row = wm * 32 + mi * 16 + (lane >> 2);
            int col = wn * 48 + ni * 8 + 2 * (lane & 3);
            sC[row * 100 + col]           = acc[mi][ni][0];
            sC[row * 100 + col + 1]       = acc[mi][ni][1];
            sC[(row + 8) * 100 + col]     = acc[mi][ni][2];
            sC[(row + 8) * 100 + col + 1] = acc[mi][ni][3];
        }
    __syncthreads();

    {
        const int m_l = tid >> 1, jh = tid & 1;
        const int mg = m0 + m_l;
        const int token = (HH == H1) ? toks[mg * S_ + t] : g_tok[mg];
        const float* pr = &proj[token * (3 * HH)];
        __half* ph0 = (__half*)hn0;
        __half* ph1 = (__half*)hn1;
        #pragma unroll
        for (int q = 0; q < 16; ++q) {
            int jl = jh * 16 + q;
            int jj = j0 + jl;
            float h_r = sC[m_l * 100 + jl]      + bhh[jj];
            float h_z = sC[m_l * 100 + 32 + jl] + bhh[HH + jj];
            float h_n = sC[m_l * 100 + 64 + jl] + bhh[2 * HH + jj];
            float r = sigmoid_(pr[jj] + h_r);
            float z = sigmoid_(pr[HH + jj] + h_z);
            float n = tanh_(pr[2 * HH + jj] + r * h_n);
            float ho = hold[mg * HH + jj];
            float hv = (1.f - z) * n + z * ho;
            hnew[mg * HH + jj] = hv;
            __half a0h, a1h;
            split2h(hv, a0h, a1h);
            ph0[mg * HH + jj] = a0h;
            ph1[mg * HH + jj] = a1h;
        }
    }
}

// ---------------- logits: split-K partial GEMM + reduce/argmax ----------------
__global__ __launch_bounds__(256)
void logits_partial_kernel(const float* __restrict__ Wfc, int pp)
{
    const float* hh = g_hh[pp ^ 1];
    const int b0 = blockIdx.x * 32;
    const int ks = blockIdx.y * 256;
    const int tid = threadIdx.x;
    const int tx = tid & 31, ty = tid >> 5;

    __shared__ float sA[32][32];
    __shared__ float sB[32][128];

    float acc[4][4];
    #pragma unroll
    for (int i = 0; i < 4; i++)
        #pragma unroll
        for (int j = 0; j < 4; j++) acc[i][j] = 0.f;

    for (int k0 = ks; k0 < ks + 256; k0 += 32) {
        {
            int r = tid >> 3, k4 = (tid & 7) * 4;
            float4 v = *(const float4*)&hh[(b0 + r) * H2 + k0 + k4];
            sA[k4 + 0][r] = v.x; sA[k4 + 1][r] = v.y;
            sA[k4 + 2][r] = v.z; sA[k4 + 3][r] = v.w;
        }
        #pragma unroll
        for (int it = 0; it < 4; ++it) {
            int idx = tid + it * 256;
            int r = idx >> 3, k4 = (idx & 7) * 4;
            float4 v = *(const float4*)&Wfc[r * H2 + k0 + k4];
            sB[k4 + 0][r] = v.x; sB[k4 + 1][r] = v.y;
            sB[k4 + 2][r] = v.z; sB[k4 + 3][r] = v.w;
        }
        __syncthreads();
        #pragma unroll
        for (int kk = 0; kk < 32; ++kk) {
            float4 a4 = *(const float4*)&sA[kk][ty * 4];
            float4 b4 = *(const float4*)&sB[kk][tx * 4];
            float a[4] = {a4.x, a4.y, a4.z, a4.w};
            float wv[4] = {b4.x, b4.y, b4.z, b4.w};
            #pragma unroll
            for (int i = 0; i < 4; i++)
                #pragma unroll
                for (int j = 0; j < 4; j++)
                    acc[i][j] = fmaf(a[i], wv[j], acc[i][j]);
        }
        __syncthreads();
    }

    #pragma unroll
    for (int i = 0; i < 4; i++)
        #pragma unroll
        for (int j = 0; j < 4; j++)
            g_part[blockIdx.y][(b0 + ty * 4 + i) * V_ + tx * 4 + j] = acc[i][j];
}

__global__ void logits_reduce_kernel(const float* __restrict__ bfc,
                                     float* __restrict__ out, int t)
{
    const int b = blockIdx.x;
    const int v = threadIdx.x;
    float s = bfc[v];
    #pragma unroll
    for (int p = 0; p < 8; p++) s += g_part[p][b * V_ + v];
    out[(b * (T_ - 1) + t) * V_ + v] = s;

    __shared__ float sv[V_];
    __shared__ int   si[V_];
    sv[v] = s; si[v] = v;
    __syncthreads();
    for (int off = 64; off > 0; off >>= 1) {
        if (v < off) {
            float o = sv[v + off]; int oi = si[v + off];
            if (o > sv[v] || (o == sv[v] && oi < si[v])) { sv[v] = o; si[v] = oi; }
        }
        __syncthreads();
    }
    if (v == 0) g_tok[b] = si[0];
}

// ---------------- init decoder ----------------
__global__ void init_dec_kernel(const int* __restrict__ tgt)
{
    int i = blockIdx.x * blockDim.x + threadIdx.x;
    if (i < B_ * H2) {
        int b = i >> 11, j = i & (H2 - 1);
        float v = (j < H1) ? g_hf[0][b * H1 + j] : g_hb[0][b * H1 + (j - H1)];
        g_hh[0][i] = v;
        __half a0, a1;
        split2h(v, a0, a1);
        ((__half*)g_hh_l0[0])[i] = a0;
        ((__half*)g_hh_l1[0])[i] = a1;
    }
    if (i < B_) g_tok[i] = tgt[i * T_];
}

// ---------------- launch ----------------
extern "C" void kernel_launch(void* const* d_in, const int* in_sizes, int n_in,
                              void* d_out, int out_size)
{
    const int*   src     = (const int*)d_in[0];
    const int*   tgt     = (const int*)d_in[1];
    const float* enc_emb = (const float*)d_in[2];
    const float* dec_emb = (const float*)d_in[3];
    const float* W_ih_f  = (const float*)d_in[4];
    const float* W_hh_f  = (const float*)d_in[5];
    const float* b_ih_f  = (const float*)d_in[6];
    const float* b_hh_f  = (const float*)d_in[7];
    const float* W_ih_b  = (const float*)d_in[8];
    const float* W_hh_b  = (const float*)d_in[9];
    const float* b_ih_b  = (const float*)d_in[10];
    const float* b_hh_b  = (const float*)d_in[11];
    const float* W_ih_d  = (const float*)d_in[12];
    const float* W_hh_d  = (const float*)d_in[13];
    const float* b_ih_d  = (const float*)d_in[14];
    const float* b_hh_d  = (const float*)d_in[15];
    const float* W_fc    = (const float*)d_in[16];
    const float* b_fc    = (const float*)d_in[17];
    float* out = (float*)d_out;

    const int SMEM = 2 * STG_BYTES;   // 112KB
    cudaFuncSetAttribute(gru_step_mma<H1>,
        cudaFuncAttributeMaxDynamicSharedMemorySize, SMEM);
    cudaFuncSetAttribute(gru_step_mma<H2>,
        cudaFuncAttributeMaxDynamicSharedMemorySize, SMEM);

    // prep (2 launches): proj tables, then weight limb-split + encoder h zero
    proj_all_kernel<<<dim3(3 * H2 / 64, 2, 3), 256>>>(
        enc_emb, dec_emb, W_ih_f, W_ih_b, W_ih_d, b_ih_f, b_ih_b, b_ih_d);
    {
        long long total = 2LL * NF + ND;
        split_all_kernel<<<(unsigned)((total + 255) / 256), 256>>>(W_hh_f, W_hh_b, W_hh_d);
    }

    for (int s = 0; s < S_; s++)
        gru_step_mma<H1><<<dim3(H1 / 32, B_ / 128, 2), 256, SMEM>>>(
            src, b_hh_f, b_hh_b, s & 1, s);
    // s=63: pp=1 -> writes buffer 0; final encoder state in buffer 0

    init_dec_kernel<<<(B_ * H2 + 255) / 256, 256>>>(tgt);

    for (int t = 0; t < T_ - 1; t++) {
        gru_step_mma<H2><<<dim3(H2 / 32, B_ / 128, 1), 256, SMEM>>>(
            (const int*)nullptr, b_hh_d, b_hh_d, t & 1, 0);
        logits_partial_kernel<<<dim3(B_ / 32, 8), 256>>>(W_fc, t & 1);
        logits_reduce_kernel<<<B_, V_>>>(b_fc, out, t);
    }
}

// round 16
// speedup vs baseline: 1.1521x; 1.0022x over previous
#include <cuda_runtime.h>
#include <cuda_fp16.h>
#include <cstdint>

// Seq2Seq GRU with HMMA (mma.sync m16n8k16 fp16->fp32), fp32-faithful via
// 2-limb fp16 decomposition x = h0 + h1; 3 limb products (A0B0+A1B0+A0B1).
// R16: limb-index made the OUTERMOST mma loop -> consecutive MMAs hit 12
//      distinct accumulators (RAW spacing 12*rt >= HMMA latency). This is the
//      dependency-chain fix; loads stay batched per ks (R15 structure).

static const int B_ = 512;
static const int S_ = 64;
static const int T_ = 32;
static const int E_ = 512;
static const int H1 = 1024;
static const int H2 = 2048;
static const int V_ = 128;

// stage layout (bytes): A0 @ 0 (16K), A1 @ 16K, B0 @ 32K (12K), B1 @ 44K; 56K total
static const int STG_BYTES = 57344;
static const int OFF_A1 = 16384;
static const int OFF_B0 = 32768;
static const int OFF_B1 = 45056;

// ---------------- device scratch ----------------
__device__ float g_proj_f[V_ * 3 * H1];
__device__ float g_proj_b[V_ * 3 * H1];
__device__ float g_proj_d[V_ * 3 * H2];
__device__ float g_hf[2][B_ * H1];
__device__ float g_hb[2][B_ * H1];
__device__ float g_hh[2][B_ * H2];
__device__ uint4 g_hf_l0[2][B_ * H1 / 8];
__device__ uint4 g_hf_l1[2][B_ * H1 / 8];
__device__ uint4 g_hb_l0[2][B_ * H1 / 8];
__device__ uint4 g_hb_l1[2][B_ * H1 / 8];
__device__ uint4 g_hh_l0[2][B_ * H2 / 8];
__device__ uint4 g_hh_l1[2][B_ * H2 / 8];
__device__ uint4 g_Wf_l0[3 * H1 * H1 / 8];
__device__ uint4 g_Wf_l1[3 * H1 * H1 / 8];
__device__ uint4 g_Wb_l0[3 * H1 * H1 / 8];
__device__ uint4 g_Wb_l1[3 * H1 * H1 / 8];
__device__ uint4 g_Wd_l0[3 * H2 * H2 / 8];
__device__ uint4 g_Wd_l1[3 * H2 * H2 / 8];
__device__ float g_part[8][B_ * V_];
__device__ int   g_tok[B_];

__device__ __forceinline__ float sigmoid_(float x) { return 1.f / (1.f + __expf(-x)); }
__device__ __forceinline__ float tanh_(float x) {
    float e = __expf(2.f * x);
    return 1.f - 2.f / (e + 1.f);
}

#define SWZ(o) ((o) ^ (((o) >> 3) & 0x70))

__device__ __forceinline__ uint32_t smem_u32(const void* p) {
    uint32_t a;
    asm("{ .reg .u64 t; cvta.to.shared.u64 t, %1; cvt.u32.u64 %0, t; }" : "=r"(a) : "l"(p));
    return a;
}
__device__ __forceinline__ void split2h(float x, __half& a0, __half& a1) {
    a0 = __float2half_rn(x);
    a1 = __float2half_rn(x - __half2float(a0));
}
__device__ __forceinline__ void cp16(uint32_t dst, const void* src) {
    asm volatile("cp.async.cg.shared.global [%0], [%1], 16;" :: "r"(dst), "l"(src));
}
__device__ __forceinline__ void cp_commit() {
    asm volatile("cp.async.commit_group;" ::: "memory");
}
template<int N>
__device__ __forceinline__ void cp_wait() {
    asm volatile("cp.async.wait_group %0;" :: "n"(N) : "memory");
}
#define LDSM_X4(r0, r1, r2, r3, addr) \
    asm volatile("ldmatrix.sync.aligned.m8n8.x4.shared.b16 {%0,%1,%2,%3}, [%4];" \
                 : "=r"(r0), "=r"(r1), "=r"(r2), "=r"(r3) : "r"(addr))
#define MMA16816(acc, af, b0, b1) \
    asm volatile("mma.sync.aligned.m16n8k16.row.col.f32.f16.f16.f32 " \
                 "{%0,%1,%2,%3}, {%4,%5,%6,%7}, {%8,%9}, {%0,%1,%2,%3};" \
                 : "+f"((acc)[0]), "+f"((acc)[1]), "+f"((acc)[2]), "+f"((acc)[3]) \
                 : "r"((af)[0]), "r"((af)[1]), "r"((af)[2]), "r"((af)[3]), \
                   "r"(b0), "r"(b1))

// ---------------- fused prep: limb-split all weights + zero encoder h ----------------
static const int NF = 3 * H1 * H1;
static const int ND = 3 * H2 * H2;
__global__ void split_all_kernel(const float* __restrict__ Wf,
                                 const float* __restrict__ Wb,
                                 const float* __restrict__ Wd)
{
    long long i = (long long)blockIdx.x * blockDim.x + threadIdx.x;
    if (i < B_ * H1) { g_hf[0][i] = 0.f; g_hb[0][i] = 0.f; }
    if (i < B_ * H1 / 8) {
        uint4 z = make_uint4(0, 0, 0, 0);
        g_hf_l0[0][i] = z; g_hf_l1[0][i] = z;
        g_hb_l0[0][i] = z; g_hb_l1[0][i] = z;
    }
    const float* src; __half *o0, *o1; long long k;
    if (i < NF)                 { src = Wf; k = i;            o0 = (__half*)g_Wf_l0; o1 = (__half*)g_Wf_l1; }
    else if (i < 2LL * NF)      { src = Wb; k = i - NF;       o0 = (__half*)g_Wb_l0; o1 = (__half*)g_Wb_l1; }
    else if (i < 2LL * NF + ND) { src = Wd; k = i - 2LL * NF; o0 = (__half*)g_Wd_l0; o1 = (__half*)g_Wd_l1; }
    else return;
    __half a0, a1;
    split2h(src[k], a0, a1);
    o0[k] = a0; o1[k] = a1;
}

// ---------------- fused projection tables: out[128][N] = Emb @ W^T + b ----------------
__global__ __launch_bounds__(256)
void proj_all_kernel(const float* __restrict__ enc_emb, const float* __restrict__ dec_emb,
                     const float* __restrict__ Wf, const float* __restrict__ Wb,
                     const float* __restrict__ Wd,
                     const float* __restrict__ bf, const float* __restrict__ bb,
                     const float* __restrict__ bd)
{
    const int which = blockIdx.z;
    const int N = (which == 2) ? 3 * H2 : 3 * H1;
    if (blockIdx.x * 64 >= N) return;
    const float* Emb = (which == 2) ? dec_emb : enc_emb;
    const float* W   = (which == 0) ? Wf : (which == 1) ? Wb : Wd;
    const float* b   = (which == 0) ? bf : (which == 1) ? bb : bd;
    float* out = (which == 0) ? g_proj_f : (which == 1) ? g_proj_b : g_proj_d;

    const int n0 = blockIdx.x * 64, m0 = blockIdx.y * 64;
    const int tid = threadIdx.x;
    const int tx = tid & 15, ty = tid >> 4;

    __shared__ float sA[32][64];
    __shared__ float sB[32][64];

    float acc[4][4];
    #pragma unroll
    for (int i = 0; i < 4; i++)
        #pragma unroll
        for (int j = 0; j < 4; j++) acc[i][j] = 0.f;

    for (int k0 = 0; k0 < E_; k0 += 32) {
        #pragma unroll
        for (int it = 0; it < 2; ++it) {
            int idx = tid + it * 256;
            int r = idx >> 3, k4 = (idx & 7) * 4;
            float4 v = *(const float4*)&Emb[(m0 + r) * E_ + k0 + k4];
            sA[k4 + 0][r] = v.x; sA[k4 + 1][r] = v.y;
            sA[k4 + 2][r] = v.z; sA[k4 + 3][r] = v.w;
        }
        #pragma unroll
        for (int it = 0; it < 2; ++it) {
            int idx = tid + it * 256;
            int r = idx >> 3, k4 = (idx & 7) * 4;
            float4 v = *(const float4*)&W[(n0 + r) * E_ + k0 + k4];
            sB[k4 + 0][r] = v.x; sB[k4 + 1][r] = v.y;
            sB[k4 + 2][r] = v.z; sB[k4 + 3][r] = v.w;
        }
        __syncthreads();
        #pragma unroll
        for (int kk = 0; kk < 32; ++kk) {
            float4 a4 = *(const float4*)&sA[kk][ty * 4];
            float4 b4 = *(const float4*)&sB[kk][tx * 4];
            float a[4] = {a4.x, a4.y, a4.z, a4.w};
            float w[4] = {b4.x, b4.y, b4.z, b4.w};
            #pragma unroll
            for (int i = 0; i < 4; i++)
                #pragma unroll
                for (int j = 0; j < 4; j++)
                    acc[i][j] = fmaf(a[i], w[j], acc[i][j]);
        }
        __syncthreads();
    }

    #pragma unroll
    for (int i = 0; i < 4; i++) {
        int m = m0 + ty * 4 + i;
        #pragma unroll
        for (int j = 0; j < 4; j++) {
            int n = n0 + tx * 4 + j;
            out[m * N + n] = acc[i][j] + b[n];
        }
    }
}

// ---------------- HMMA GRU step: 8 warps x (M32 x N48), RAW-spaced mma ----------------
// CTA: 128 batch (blockIdx.y) x 32 j (blockIdx.x) x 3 gates -> N=96.
// 2 stages x 56KB; epilogue reuses SMEM as fp32 C [128][100].
template<int HH>
__global__ __launch_bounds__(256, 2)
void gru_step_mma(const int* __restrict__ toks, const float* __restrict__ bhh_a,
                  const float* __restrict__ bhh_b, int pp, int s)
{
    extern __shared__ char smem[];
    const uint32_t su = smem_u32(smem);
    const int tid = threadIdx.x;

    const uint4 *w0, *w1, *h0p, *h1p;
    uint4 *hn0, *hn1;
    const float *hold, *bhh, *proj;
    float* hnew;
    int t = 0;
    if (HH == H1) {
        const int dir = blockIdx.z;
        if (dir == 0) {
            w0 = g_Wf_l0; w1 = g_Wf_l1;
            h0p = g_hf_l0[pp]; h1p = g_hf_l1[pp];
            hn0 = g_hf_l0[pp ^ 1]; hn1 = g_hf_l1[pp ^ 1];
            hold = g_hf[pp]; hnew = g_hf[pp ^ 1];
            bhh = bhh_a; proj = g_proj_f; t = s;
        } else {
            w0 = g_Wb_l0; w1 = g_Wb_l1;
            h0p = g_hb_l0[pp]; h1p = g_hb_l1[pp];
            hn0 = g_hb_l0[pp ^ 1]; hn1 = g_hb_l1[pp ^ 1];
            hold = g_hb[pp]; hnew = g_hb[pp ^ 1];
            bhh = bhh_b; proj = g_proj_b; t = S_ - 1 - s;
        }
    } else {
        w0 = g_Wd_l0; w1 = g_Wd_l1;
        h0p = g_hh_l0[pp]; h1p = g_hh_l1[pp];
        hn0 = g_hh_l0[pp ^ 1]; hn1 = g_hh_l1[pp ^ 1];
        hold = g_hh[pp]; hnew = g_hh[pp ^ 1];
        bhh = bhh_a; proj = g_proj_d;
    }

    const int m0 = blockIdx.y * 128;
    const int j0 = blockIdx.x * 32;

    const int w = tid >> 5, lane = tid & 31;
    const int wm = w >> 1, wn = w & 1;       // 4 x 2 warp grid: M=32, N=48 per warp

    float acc[2][6][4];
    #pragma unroll
    for (int mi = 0; mi < 2; ++mi)
        #pragma unroll
        for (int ni = 0; ni < 6; ++ni)
            #pragma unroll
            for (int q = 0; q < 4; ++q) acc[mi][ni][q] = 0.f;

    const int NCH = HH / 64;

    auto stage_load = [&](int c, int st) {
        const int k0 = c * 64;
        const uint32_t sb = su + st * STG_BYTES;
        #pragma unroll
        for (int it = 0; it < 4; ++it) {
            int idx = tid + it * 256;
            int r = idx >> 3, kb = idx & 7;
            int gi = ((m0 + r) * HH + k0) / 8 + kb;
            uint32_t o = SWZ((uint32_t)(r * 128 + kb * 16));
            cp16(sb + o, &h0p[gi]);
            cp16(sb + OFF_A1 + o, &h1p[gi]);
        }
        #pragma unroll
        for (int it = 0; it < 3; ++it) {
            int idx = tid + it * 256;
            int rsm = idx >> 3, kb = idx & 7;
            int g = rsm >> 5, jl = rsm & 31;
            int gi = ((g * HH + j0 + jl) * HH + k0) / 8 + kb;
            uint32_t o = SWZ((uint32_t)(rsm * 128 + kb * 16));
            cp16(sb + OFF_B0 + o, &w0[gi]);
            cp16(sb + OFF_B1 + o, &w1[gi]);
        }
    };

    stage_load(0, 0);
    cp_commit();

    // B ldmatrix.x4 lane mapping: quads 0,1 -> limb0 (k lo/hi 16B); quads 2,3 -> limb1
    const int bquad = lane >> 3;
    const uint32_t blimb_off = (bquad >= 2) ? (uint32_t)OFF_B1 : (uint32_t)OFF_B0;
    const uint32_t bk_off = (uint32_t)(bquad & 1) * 16;
    const int bn_lane = lane & 7;
    const int arow_l = lane & 15;
    const uint32_t acol16 = (uint32_t)((lane >> 4) << 4);

    for (int c = 0; c < NCH; ++c) {
        if (c + 1 < NCH) {
            stage_load(c + 1, (c + 1) & 1);
            cp_commit();
            cp_wait<1>();
        } else {
            cp_wait<0>();
        }
        __syncthreads();

        const uint32_t sb = su + (c & 1) * STG_BYTES;
        #pragma unroll
        for (int ks = 0; ks < 4; ++ks) {
            // ---- batch loads for this ks: 4 A ldsm + 6 B ldsm ----
            uint32_t a0[2][4], a1[2][4], bf[6][4];
            #pragma unroll
            for (int mi = 0; mi < 2; ++mi) {
                int row = wm * 32 + mi * 16 + arow_l;
                uint32_t o = SWZ((uint32_t)(row * 128 + ks * 32 + acol16));
                LDSM_X4(a0[mi][0], a0[mi][1], a0[mi][2], a0[mi][3], sb + o);
                LDSM_X4(a1[mi][0], a1[mi][1], a1[mi][2], a1[mi][3], sb + OFF_A1 + o);
            }
            #pragma unroll
            for (int ni = 0; ni < 6; ++ni) {
                int nrow = wn * 48 + ni * 8 + bn_lane;
                uint32_t baddr = sb + blimb_off
                               + SWZ((uint32_t)(nrow * 128 + ks * 32 + bk_off));
                LDSM_X4(bf[ni][0], bf[ni][1], bf[ni][2], bf[ni][3], baddr);
            }
            // ---- 36 MMA, limb index OUTERMOST: consecutive MMAs hit 12
            //      distinct accumulators -> no RAW stall inside the burst ----
            #pragma unroll
            for (int ni = 0; ni < 6; ++ni)
                #pragma unroll
                for (int mi = 0; mi < 2; ++mi)
                    MMA16816(acc[mi][ni], a0[mi], bf[ni][0], bf[ni][1]);   // A0*B0
            #pragma unroll
            for (int ni = 0; ni < 6; ++ni)
                #pragma unroll
                for (int mi = 0; mi < 2; ++mi)
                    MMA16816(acc[mi][ni], a1[mi], bf[ni][0], bf[ni][1]);   // A1*B0
            #pragma unroll
            for (int ni = 0; ni < 6; ++ni)
                #pragma unroll
                for (int mi = 0; mi < 2; ++mi)
                    MMA16816(acc[mi][ni], a0[mi], bf[ni][2], bf[ni][3]);   // A0*B1
        }
        __syncthreads();
    }

    // ---- epilogue: C -> SMEM roundtrip (co-locate r/z/n), then gate math ----
    float* sC = (float*)smem;   // [128][100]
    #pragma unroll
    for (int mi = 0; mi < 2; ++mi)
        #pragma unroll
        for (int ni = 0; ni < 6; ++ni) {
            int row = wm * 32 + mi * 16 + (lane >> 2);
            int col = wn * 48 + ni * 8 + 2 * (lane & 3);
            sC[row * 100 + col]           = acc[mi][ni][0];
            sC[row * 100 + col + 1]       = acc[mi][ni][1];
            sC[(row + 8) * 100 + col]     = acc[mi][ni][2];
            sC[(row + 8) * 100 + col + 1] = acc[mi][ni][3];
        }
    __syncthreads();

    {
        const int m_l = tid >> 1, jh = tid & 1;
        const int mg = m0 + m_l;
        const int token = (HH == H1) ? toks[mg * S_ + t] : g_tok[mg];
        const float* pr = &proj[token * (3 * HH)];
        __half* ph0 = (__half*)hn0;
        __half* ph1 = (__half*)hn1;
        #pragma unroll
        for (int q = 0; q < 16; ++q) {
            int jl = jh * 16 + q;
            int jj = j0 + jl;
            float h_r = sC[m_l * 100 + jl]      + bhh[jj];
            float h_z = sC[m_l * 100 + 32 + jl] + bhh[HH + jj];
            float h_n = sC[m_l * 100 + 64 + jl] + bhh[2 * HH + jj];
            float r = sigmoid_(pr[jj] + h_r);
            float z = sigmoid_(pr[HH + jj] + h_z);
            float n = tanh_(pr[2 * HH + jj] + r * h_n);
            float ho = hold[mg * HH + jj];
            float hv = (1.f - z) * n + z * ho;
            hnew[mg * HH + jj] = hv;
            __half a0h, a1h;
            split2h(hv, a0h, a1h);
            ph0[mg * HH + jj] = a0h;
            ph1[mg * HH + jj] = a1h;
        }
    }
}

// ---------------- logits: split-K partial GEMM + reduce/argmax ----------------
__global__ __launch_bounds__(256)
void logits_partial_kernel(const float* __restrict__ Wfc, int pp)
{
    const float* hh = g_hh[pp ^ 1];
    const int b0 = blockIdx.x * 32;
    const int ks = blockIdx.y * 256;
    const int tid = threadIdx.x;
    const int tx = tid & 31, ty = tid >> 5;

    __shared__ float sA[32][32];
    __shared__ float sB[32][128];

    float acc[4][4];
    #pragma unroll
    for (int i = 0; i < 4; i++)
        #pragma unroll
        for (int j = 0; j < 4; j++) acc[i][j] = 0.f;

    for (int k0 = ks; k0 < ks + 256; k0 += 32) {
        {
            int r = tid >> 3, k4 = (tid & 7) * 4;
            float4 v = *(const float4*)&hh[(b0 + r) * H2 + k0 + k4];
            sA[k4 + 0][r] = v.x; sA[k4 + 1][r] = v.y;
            sA[k4 + 2][r] = v.z; sA[k4 + 3][r] = v.w;
        }
        #pragma unroll
        for (int it = 0; it < 4; ++it) {
            int idx = tid + it * 256;
            int r = idx >> 3, k4 = (idx & 7) * 4;
            float4 v = *(const float4*)&Wfc[r * H2 + k0 + k4];
            sB[k4 + 0][r] = v.x; sB[k4 + 1][r] = v.y;
            sB[k4 + 2][r] = v.z; sB[k4 + 3][r] = v.w;
        }
        __syncthreads();
        #pragma unroll
        for (int kk = 0; kk < 32; ++kk) {
            float4 a4 = *(const float4*)&sA[kk][ty * 4];
            float4 b4 = *(const float4*)&sB[kk][tx * 4];
            float a[4] = {a4.x, a4.y, a4.z, a4.w};
            float wv[4] = {b4.x, b4.y, b4.z, b4.w};
            #pragma unroll
            for (int i = 0; i < 4; i++)
                #pragma unroll
                for (int j = 0; j < 4; j++)
                    acc[i][j] = fmaf(a[i], wv[j], acc[i][j]);
        }
        __syncthreads();
    }

    #pragma unroll
    for (int i = 0; i < 4; i++)
        #pragma unroll
        for (int j = 0; j < 4; j++)
            g_part[blockIdx.y][(b0 + ty * 4 + i) * V_ + tx * 4 + j] = acc[i][j];
}

__global__ void logits_reduce_kernel(const float* __restrict__ bfc,
                                     float* __restrict__ out, int t)
{
    const int b = blockIdx.x;
    const int v = threadIdx.x;
    float s = bfc[v];
    #pragma unroll
    for (int p = 0; p < 8; p++) s += g_part[p][b * V_ + v];
    out[(b * (T_ - 1) + t) * V_ + v] = s;

    __shared__ float sv[V_];
    __shared__ int   si[V_];
    sv[v] = s; si[v] = v;
    __syncthreads();
    for (int off = 64; off > 0; off >>= 1) {
        if (v < off) {
            float o = sv[v + off]; int oi = si[v + off];
            if (o > sv[v] || (o == sv[v] && oi < si[v])) { sv[v] = o; si[v] = oi; }
        }
        __syncthreads();
    }
    if (v == 0) g_tok[b] = si[0];
}

// ---------------- init decoder ----------------
__global__ void init_dec_kernel(const int* __restrict__ tgt)
{
    int i = blockIdx.x * blockDim.x + threadIdx.x;
    if (i < B_ * H2) {
        int b = i >> 11, j = i & (H2 - 1);
        float v = (j < H1) ? g_hf[0][b * H1 + j] : g_hb[0][b * H1 + (j - H1)];
        g_hh[0][i] = v;
        __half a0, a1;
        split2h(v, a0, a1);
        ((__half*)g_hh_l0[0])[i] = a0;
        ((__half*)g_hh_l1[0])[i] = a1;
    }
    if (i < B_) g_tok[i] = tgt[i * T_];
}

// ---------------- launch ----------------
extern "C" void kernel_launch(void* const* d_in, const int* in_sizes, int n_in,
                              void* d_out, int out_size)
{
    const int*   src     = (const int*)d_in[0];
    const int*   tgt     = (const int*)d_in[1];
    const float* enc_emb = (const float*)d_in[2];
    const float* dec_emb = (const float*)d_in[3];
    const float* W_ih_f  = (const float*)d_in[4];
    const float* W_hh_f  = (const float*)d_in[5];
    const float* b_ih_f  = (const float*)d_in[6];
    const float* b_hh_f  = (const float*)d_in[7];
    const float* W_ih_b  = (const float*)d_in[8];
    const float* W_hh_b  = (const float*)d_in[9];
    const float* b_ih_b  = (const float*)d_in[10];
    const float* b_hh_b  = (const float*)d_in[11];
    const float* W_ih_d  = (const float*)d_in[12];
    const float* W_hh_d  = (const float*)d_in[13];
    const float* b_ih_d  = (const float*)d_in[14];
    const float* b_hh_d  = (const float*)d_in[15];
    const float* W_fc    = (const float*)d_in[16];
    const float* b_fc    = (const float*)d_in[17];
    float* out = (float*)d_out;

    const int SMEM = 2 * STG_BYTES;   // 112KB
    cudaFuncSetAttribute(gru_step_mma<H1>,
        cudaFuncAttributeMaxDynamicSharedMemorySize, SMEM);
    cudaFuncSetAttribute(gru_step_mma<H2>,
        cudaFuncAttributeMaxDynamicSharedMemorySize, SMEM);

    // prep (2 launches): proj tables, then weight limb-split + encoder h zero
    proj_all_kernel<<<dim3(3 * H2 / 64, 2, 3), 256>>>(
        enc_emb, dec_emb, W_ih_f, W_ih_b, W_ih_d, b_ih_f, b_ih_b, b_ih_d);
    {
        long long total = 2LL * NF + ND;
        split_all_kernel<<<(unsigned)((total + 255) / 256), 256>>>(W_hh_f, W_hh_b, W_hh_d);
    }

    for (int s = 0; s < S_; s++)
        gru_step_mma<H1><<<dim3(H1 / 32, B_ / 128, 2), 256, SMEM>>>(
            src, b_hh_f, b_hh_b, s & 1, s);
    // s=63: pp=1 -> writes buffer 0; final encoder state in buffer 0

    init_dec_kernel<<<(B_ * H2 + 255) / 256, 256>>>(tgt);

    for (int t = 0; t < T_ - 1; t++) {
        gru_step_mma<H2><<<dim3(H2 / 32, B_ / 128, 1), 256, SMEM>>>(
            (const int*)nullptr, b_hh_d, b_hh_d, t & 1, 0);
        logits_partial_kernel<<<dim3(B_ / 32, 8), 256>>>(W_fc, t & 1);
        logits_reduce_kernel<<<B_, V_>>>(b_fc, out, t);
    }
}

// round 17
// speedup vs baseline: 1.2119x; 1.0520x over previous
#include <cuda_runtime.h>
#include <cuda_fp16.h>
#include <cstdint>

// Seq2Seq GRU with HMMA (mma.sync m16n8k16 fp16->fp32), fp32-faithful via
// 2-limb fp16 decomposition x = h0 + h1; 3 limb products (A0B0+A1B0+A0B1).
// R17: occupancy play. 512 threads/CTA, 16 warps (4m x 4n), warp tile M32xN24,
//      <=64 regs/thread -> 32 warps/SM (2 CTAs). Per-acc product order kept
//      bit-identical. Grid/SMEM layout unchanged.

static const int B_ = 512;
static const int S_ = 64;
static const int T_ = 32;
static const int E_ = 512;
static const int H1 = 1024;
static const int H2 = 2048;
static const int V_ = 128;

// stage layout (bytes): A0 @ 0 (16K), A1 @ 16K, B0 @ 32K (12K), B1 @ 44K; 56K total
static const int STG_BYTES = 57344;
static const int OFF_A1 = 16384;
static const int OFF_B0 = 32768;
static const int OFF_B1 = 45056;

// ---------------- device scratch ----------------
__device__ float g_proj_f[V_ * 3 * H1];
__device__ float g_proj_b[V_ * 3 * H1];
__device__ float g_proj_d[V_ * 3 * H2];
__device__ float g_hf[2][B_ * H1];
__device__ float g_hb[2][B_ * H1];
__device__ float g_hh[2][B_ * H2];
__device__ uint4 g_hf_l0[2][B_ * H1 / 8];
__device__ uint4 g_hf_l1[2][B_ * H1 / 8];
__device__ uint4 g_hb_l0[2][B_ * H1 / 8];
__device__ uint4 g_hb_l1[2][B_ * H1 / 8];
__device__ uint4 g_hh_l0[2][B_ * H2 / 8];
__device__ uint4 g_hh_l1[2][B_ * H2 / 8];
__device__ uint4 g_Wf_l0[3 * H1 * H1 / 8];
__device__ uint4 g_Wf_l1[3 * H1 * H1 / 8];
__device__ uint4 g_Wb_l0[3 * H1 * H1 / 8];
__device__ uint4 g_Wb_l1[3 * H1 * H1 / 8];
__device__ uint4 g_Wd_l0[3 * H2 * H2 / 8];
__device__ uint4 g_Wd_l1[3 * H2 * H2 / 8];
__device__ float g_part[8][B_ * V_];
__device__ int   g_tok[B_];

__device__ __forceinline__ float sigmoid_(float x) { return 1.f / (1.f + __expf(-x)); }
__device__ __forceinline__ float tanh_(float x) {
    float e = __expf(2.f * x);
    return 1.f - 2.f / (e + 1.f);
}

#define SWZ(o) ((o) ^ (((o) >> 3) & 0x70))

__device__ __forceinline__ uint32_t smem_u32(const void* p) {
    uint32_t a;
    asm("{ .reg .u64 t; cvta.to.shared.u64 t, %1; cvt.u32.u64 %0, t; }" : "=r"(a) : "l"(p));
    return a;
}
__device__ __forceinline__ void split2h(float x, __half& a0, __half& a1) {
    a0 = __float2half_rn(x);
    a1 = __float2half_rn(x - __half2float(a0));
}
__device__ __forceinline__ void cp16(uint32_t dst, const void* src) {
    asm volatile("cp.async.cg.shared.global [%0], [%1], 16;" :: "r"(dst), "l"(src));
}
__device__ __forceinline__ void cp_commit() {
    asm volatile("cp.async.commit_group;" ::: "memory");
}
template<int N>
__device__ __forceinline__ void cp_wait() {
    asm volatile("cp.async.wait_group %0;" :: "n"(N) : "memory");
}
#define LDSM_X4(r0, r1, r2, r3, addr) \
    asm volatile("ldmatrix.sync.aligned.m8n8.x4.shared.b16 {%0,%1,%2,%3}, [%4];" \
                 : "=r"(r0), "=r"(r1), "=r"(r2), "=r"(r3) : "r"(addr))
#define MMA16816(acc, af, b0, b1) \
    asm volatile("mma.sync.aligned.m16n8k16.row.col.f32.f16.f16.f32 " \
                 "{%0,%1,%2,%3}, {%4,%5,%6,%7}, {%8,%9}, {%0,%1,%2,%3};" \
                 : "+f"((acc)[0]), "+f"((acc)[1]), "+f"((acc)[2]), "+f"((acc)[3]) \
                 : "r"((af)[0]), "r"((af)[1]), "r"((af)[2]), "r"((af)[3]), \
                   "r"(b0), "r"(b1))

// ---------------- fused prep: limb-split all weights + zero encoder h ----------------
static const int NF = 3 * H1 * H1;
static const int ND = 3 * H2 * H2;
__global__ void split_all_kernel(const float* __restrict__ Wf,
                                 const float* __restrict__ Wb,
                                 const float* __restrict__ Wd)
{
    long long i = (long long)blockIdx.x * blockDim.x + threadIdx.x;
    if (i < B_ * H1) { g_hf[0][i] = 0.f; g_hb[0][i] = 0.f; }
    if (i < B_ * H1 / 8) {
        uint4 z = make_uint4(0, 0, 0, 0);
        g_hf_l0[0][i] = z; g_hf_l1[0][i] = z;
        g_hb_l0[0][i] = z; g_hb_l1[0][i] = z;
    }
    const float* src; __half *o0, *o1; long long k;
    if (i < NF)                 { src = Wf; k = i;            o0 = (__half*)g_Wf_l0; o1 = (__half*)g_Wf_l1; }
    else if (i < 2LL * NF)      { src = Wb; k = i - NF;       o0 = (__half*)g_Wb_l0; o1 = (__half*)g_Wb_l1; }
    else if (i < 2LL * NF + ND) { src = Wd; k = i - 2LL * NF; o0 = (__half*)g_Wd_l0; o1 = (__half*)g_Wd_l1; }
    else return;
    __half a0, a1;
    split2h(src[k], a0, a1);
    o0[k] = a0; o1[k] = a1;
}

// ---------------- fused projection tables: out[128][N] = Emb @ W^T + b ----------------
__global__ __launch_bounds__(256)
void proj_all_kernel(const float* __restrict__ enc_emb, const float* __restrict__ dec_emb,
                     const float* __restrict__ Wf, const float* __restrict__ Wb,
                     const float* __restrict__ Wd,
                     const float* __restrict__ bf, const float* __restrict__ bb,
                     const float* __restrict__ bd)
{
    const int which = blockIdx.z;
    const int N = (which == 2) ? 3 * H2 : 3 * H1;
    if (blockIdx.x * 64 >= N) return;
    const float* Emb = (which == 2) ? dec_emb : enc_emb;
    const float* W   = (which == 0) ? Wf : (which == 1) ? Wb : Wd;
    const float* b   = (which == 0) ? bf : (which == 1) ? bb : bd;
    float* out = (which == 0) ? g_proj_f : (which == 1) ? g_proj_b : g_proj_d;

    const int n0 = blockIdx.x * 64, m0 = blockIdx.y * 64;
    const int tid = threadIdx.x;
    const int tx = tid & 15, ty = tid >> 4;

    __shared__ float sA[32][64];
    __shared__ float sB[32][64];

    float acc[4][4];
    #pragma unroll
    for (int i = 0; i < 4; i++)
        #pragma unroll
        for (int j = 0; j < 4; j++) acc[i][j] = 0.f;

    for (int k0 = 0; k0 < E_; k0 += 32) {
        #pragma unroll
        for (int it = 0; it < 2; ++it) {
            int idx = tid + it * 256;
            int r = idx >> 3, k4 = (idx & 7) * 4;
            float4 v = *(const float4*)&Emb[(m0 + r) * E_ + k0 + k4];
            sA[k4 + 0][r] = v.x; sA[k4 + 1][r] = v.y;
            sA[k4 + 2][r] = v.z; sA[k4 + 3][r] = v.w;
        }
        #pragma unroll
        for (int it = 0; it < 2; ++it) {
            int idx = tid + it * 256;
            int r = idx >> 3, k4 = (idx & 7) * 4;
            float4 v = *(const float4*)&W[(n0 + r) * E_ + k0 + k4];
            sB[k4 + 0][r] = v.x; sB[k4 + 1][r] = v.y;
            sB[k4 + 2][r] = v.z; sB[k4 + 3][r] = v.w;
        }
        __syncthreads();
        #pragma unroll
        for (int kk = 0; kk < 32; ++kk) {
            float4 a4 = *(const float4*)&sA[kk][ty * 4];
            float4 b4 = *(const float4*)&sB[kk][tx * 4];
            float a[4] = {a4.x, a4.y, a4.z, a4.w};
            float w[4] = {b4.x, b4.y, b4.z, b4.w};
            #pragma unroll
            for (int i = 0; i < 4; i++)
                #pragma unroll
                for (int j = 0; j < 4; j++)
                    acc[i][j] = fmaf(a[i], w[j], acc[i][j]);
        }
        __syncthreads();
    }

    #pragma unroll
    for (int i = 0; i < 4; i++) {
        int m = m0 + ty * 4 + i;
        #pragma unroll
        for (int j = 0; j < 4; j++) {
            int n = n0 + tx * 4 + j;
            out[m * N + n] = acc[i][j] + b[n];
        }
    }
}

// ---------------- HMMA GRU step: 16 warps x (M32 x N24), 512 threads ----------------
// CTA: 128 batch (blockIdx.y) x 32 j (blockIdx.x) x 3 gates -> N=96.
// 2 stages x 56KB; epilogue reuses SMEM as fp32 C [128][100].
template<int HH>
__global__ __launch_bounds__(512, 2)
void gru_step_mma(const int* __restrict__ toks, const float* __restrict__ bhh_a,
                  const float* __restrict__ bhh_b, int pp, int s)
{
    extern __shared__ char smem[];
    const uint32_t su = smem_u32(smem);
    const int tid = threadIdx.x;

    const uint4 *w0, *w1, *h0p, *h1p;
    uint4 *hn0, *hn1;
    const float *hold, *bhh, *proj;
    float* hnew;
    int t = 0;
    if (HH == H1) {
        const int dir = blockIdx.z;
        if (dir == 0) {
            w0 = g_Wf_l0; w1 = g_Wf_l1;
            h0p = g_hf_l0[pp]; h1p = g_hf_l1[pp];
            hn0 = g_hf_l0[pp ^ 1]; hn1 = g_hf_l1[pp ^ 1];
            hold = g_hf[pp]; hnew = g_hf[pp ^ 1];
            bhh = bhh_a; proj = g_proj_f; t = s;
        } else {
            w0 = g_Wb_l0; w1 = g_Wb_l1;
            h0p = g_hb_l0[pp]; h1p = g_hb_l1[pp];
            hn0 = g_hb_l0[pp ^ 1]; hn1 = g_hb_l1[pp ^ 1];
            hold = g_hb[pp]; hnew = g_hb[pp ^ 1];
            bhh = bhh_b; proj = g_proj_b; t = S_ - 1 - s;
        }
    } else {
        w0 = g_Wd_l0; w1 = g_Wd_l1;
        h0p = g_hh_l0[pp]; h1p = g_hh_l1[pp];
        hn0 = g_hh_l0[pp ^ 1]; hn1 = g_hh_l1[pp ^ 1];
        hold = g_hh[pp]; hnew = g_hh[pp ^ 1];
        bhh = bhh_a; proj = g_proj_d;
    }

    const int m0 = blockIdx.y * 128;
    const int j0 = blockIdx.x * 32;

    const int w = tid >> 5, lane = tid & 31;
    const int wm = w >> 2, wn = w & 3;       // 4 x 4 warp grid: M=32, N=24 per warp

    float acc[2][3][4];
    #pragma unroll
    for (int mi = 0; mi < 2; ++mi)
        #pragma unroll
        for (int ni = 0; ni < 3; ++ni)
            #pragma unroll
            for (int q = 0; q < 4; ++q) acc[mi][ni][q] = 0.f;

    const int NCH = HH / 64;

    auto stage_load = [&](int c, int st) {
        const int k0 = c * 64;
        const uint32_t sb = su + st * STG_BYTES;
        #pragma unroll
        for (int it = 0; it < 2; ++it) {
            int idx = tid + it * 512;
            int r = idx >> 3, kb = idx & 7;
            int gi = ((m0 + r) * HH + k0) / 8 + kb;
            uint32_t o = SWZ((uint32_t)(r * 128 + kb * 16));
            cp16(sb + o, &h0p[gi]);
            cp16(sb + OFF_A1 + o, &h1p[gi]);
        }
        #pragma unroll
        for (int it = 0; it < 2; ++it) {
            int idx = tid + it * 512;
            if (idx < 768) {
                int rsm = idx >> 3, kb = idx & 7;
                int g = rsm >> 5, jl = rsm & 31;
                int gi = ((g * HH + j0 + jl) * HH + k0) / 8 + kb;
                uint32_t o = SWZ((uint32_t)(rsm * 128 + kb * 16));
                cp16(sb + OFF_B0 + o, &w0[gi]);
                cp16(sb + OFF_B1 + o, &w1[gi]);
            }
        }
    };

    stage_load(0, 0);
    cp_commit();

    // B ldmatrix.x4 lane mapping: quads 0,1 -> limb0 (k lo/hi 16B); quads 2,3 -> limb1
    const int bquad = lane >> 3;
    const uint32_t blimb_off = (bquad >= 2) ? (uint32_t)OFF_B1 : (uint32_t)OFF_B0;
    const uint32_t bk_off = (uint32_t)(bquad & 1) * 16;
    const int bn_lane = lane & 7;
    const int arow_l = lane & 15;
    const uint32_t acol16 = (uint32_t)((lane >> 4) << 4);

    for (int c = 0; c < NCH; ++c) {
        if (c + 1 < NCH) {
            stage_load(c + 1, (c + 1) & 1);
            cp_commit();
            cp_wait<1>();
        } else {
            cp_wait<0>();
        }
        __syncthreads();

        const uint32_t sb = su + (c & 1) * STG_BYTES;
        #pragma unroll
        for (int ks = 0; ks < 4; ++ks) {
            uint32_t a0[2][4], a1[2][4];
            #pragma unroll
            for (int mi = 0; mi < 2; ++mi) {
                int row = wm * 32 + mi * 16 + arow_l;
                uint32_t o = SWZ((uint32_t)(row * 128 + ks * 32 + acol16));
                LDSM_X4(a0[mi][0], a0[mi][1], a0[mi][2], a0[mi][3], sb + o);
                LDSM_X4(a1[mi][0], a1[mi][1], a1[mi][2], a1[mi][3], sb + OFF_A1 + o);
            }
            // per ni: one B ldsm.x4, then 6 MMA (per-acc order A0B0, A1B0, A0B1)
            #pragma unroll
            for (int ni = 0; ni < 3; ++ni) {
                int nrow = wn * 24 + ni * 8 + bn_lane;
                uint32_t baddr = sb + blimb_off
                               + SWZ((uint32_t)(nrow * 128 + ks * 32 + bk_off));
                uint32_t b00, b01, b10, b11;
                LDSM_X4(b00, b01, b10, b11, baddr);
                MMA16816(acc[0][ni], a0[0], b00, b01);
                MMA16816(acc[1][ni], a0[1], b00, b01);
                MMA16816(acc[0][ni], a1[0], b00, b01);
                MMA16816(acc[1][ni], a1[1], b00, b01);
                MMA16816(acc[0][ni], a0[0], b10, b11);
                MMA16816(acc[1][ni], a0[1], b10, b11);
            }
        }
        __syncthreads();
    }

    // ---- epilogue: C -> SMEM roundtrip (co-locate r/z/n), then gate math ----
    float* sC = (float*)smem;   // [128][100]
    #pragma unroll
    for (int mi = 0; mi < 2; ++mi)
        #pragma unroll
        for (int ni = 0; ni < 3; ++ni) {
            int row = wm * 32 + mi * 16 + (lane >> 2);
            int col = wn * 24 + ni * 8 + 2 * (lane & 3);
            sC[row * 100 + col]           = acc[mi][ni][0];
            sC[row * 100 + col + 1]       = acc[mi][ni][1];
            sC[(row + 8) * 100 + col]     = acc[mi][ni][2];
            sC[(row + 8) * 100 + col + 1] = acc[mi][ni][3];
        }
    __syncthreads();

    {
        const int m_l = tid >> 2, jh = tid & 3;
        const int mg = m0 + m_l;
        const int token = (HH == H1) ? toks[mg * S_ + t] : g_tok[mg];
        const float* pr = &proj[token * (3 * HH)];
        __half* ph0 = (__half*)hn0;
        __half* ph1 = (__half*)hn1;
        #pragma unroll
        for (int q = 0; q < 8; ++q) {
            int jl = jh * 8 + q;
            int jj = j0 + jl;
            float h_r = sC[m_l * 100 + jl]      + bhh[jj];
            float h_z = sC[m_l * 100 + 32 + jl] + bhh[HH + jj];
            float h_n = sC[m_l * 100 + 64 + jl] + bhh[2 * HH + jj];
            float r = sigmoid_(pr[jj] + h_r);
            float z = sigmoid_(pr[HH + jj] + h_z);
            float n = tanh_(pr[2 * HH + jj] + r * h_n);
            float ho = hold[mg * HH + jj];
            float hv = (1.f - z) * n + z * ho;
            hnew[mg * HH + jj] = hv;
            __half a0h, a1h;
            split2h(hv, a0h, a1h);
            ph0[mg * HH + jj] = a0h;
            ph1[mg * HH + jj] = a1h;
        }
    }
}

// ---------------- logits: split-K partial GEMM + reduce/argmax ----------------
__global__ __launch_bounds__(256)
void logits_partial_kernel(const float* __restrict__ Wfc, int pp)
{
    const float* hh = g_hh[pp ^ 1];
    const int b0 = blockIdx.x * 32;
    const int ks = blockIdx.y * 256;
    const int tid = threadIdx.x;
    const int tx = tid & 31, ty = tid >> 5;

    __shared__ float sA[32][32];
    __shared__ float sB[32][128];

    float acc[4][4];
    #pragma unroll
    for (int i = 0; i < 4; i++)
        #pragma unroll
        for (int j = 0; j < 4; j++) acc[i][j] = 0.f;

    for (int k0 = ks; k0 < ks + 256; k0 += 32) {
        {
            int r = tid >> 3, k4 = (tid & 7) * 4;
            float4 v = *(const float4*)&hh[(b0 + r) * H2 + k0 + k4];
            sA[k4 + 0][r] = v.x; sA[k4 + 1][r] = v.y;
            sA[k4 + 2][r] = v.z; sA[k4 + 3][r] = v.w;
        }
        #pragma unroll
        for (int it = 0; it < 4; ++it) {
            int idx = tid + it * 256;
            int r = idx >> 3, k4 = (idx & 7) * 4;
            float4 v = *(const float4*)&Wfc[r * H2 + k0 + k4];
            sB[k4 + 0][r] = v.x; sB[k4 + 1][r] = v.y;
            sB[k4 + 2][r] = v.z; sB[k4 + 3][r] = v.w;
        }
        __syncthreads();
        #pragma unroll
        for (int kk = 0; kk < 32; ++kk) {
            float4 a4 = *(const float4*)&sA[kk][ty * 4];
            float4 b4 = *(const float4*)&sB[kk][tx * 4];
            float a[4] = {a4.x, a4.y, a4.z, a4.w};
            float wv[4] = {b4.x, b4.y, b4.z, b4.w};
            #pragma unroll
            for (int i = 0; i < 4; i++)
                #pragma unroll
                for (int j = 0; j < 4; j++)
                    acc[i][j] = fmaf(a[i], wv[j], acc[i][j]);
        }
        __syncthreads();
    }

    #pragma unroll
    for (int i = 0; i < 4; i++)
        #pragma unroll
        for (int j = 0; j < 4; j++)
            g_part[blockIdx.y][(b0 + ty * 4 + i) * V_ + tx * 4 + j] = acc[i][j];
}

__global__ void logits_reduce_kernel(const float* __restrict__ bfc,
                                     float* __restrict__ out, int t)
{
    const int b = blockIdx.x;
    const int v = threadIdx.x;
    float s = bfc[v];
    #pragma unroll
    for (int p = 0; p < 8; p++) s += g_part[p][b * V_ + v];
    out[(b * (T_ - 1) + t) * V_ + v] = s;

    __shared__ float sv[V_];
    __shared__ int   si[V_];
    sv[v] = s; si[v] = v;
    __syncthreads();
    for (int off = 64; off > 0; off >>= 1) {
        if (v < off) {
            float o = sv[v + off]; int oi = si[v + off];
            if (o > sv[v] || (o == sv[v] && oi < si[v])) { sv[v] = o; si[v] = oi; }
        }
        __syncthreads();
    }
    if (v == 0) g_tok[b] = si[0];
}

// ---------------- init decoder ----------------
__global__ void init_dec_kernel(const int* __restrict__ tgt)
{
    int i = blockIdx.x * blockDim.x + threadIdx.x;
    if (i < B_ * H2) {
        int b = i >> 11, j = i & (H2 - 1);
        float v = (j < H1) ? g_hf[0][b * H1 + j] : g_hb[0][b * H1 + (j - H1)];
        g_hh[0][i] = v;
        __half a0, a1;
        split2h(v, a0, a1);
        ((__half*)g_hh_l0[0])[i] = a0;
        ((__half*)g_hh_l1[0])[i] = a1;
    }
    if (i < B_) g_tok[i] = tgt[i * T_];
}

// ---------------- launch ----------------
extern "C" void kernel_launch(void* const* d_in, const int* in_sizes, int n_in,
                              void* d_out, int out_size)
{
    const int*   src     = (const int*)d_in[0];
    const int*   tgt     = (const int*)d_in[1];
    const float* enc_emb = (const float*)d_in[2];
    const float* dec_emb = (const float*)d_in[3];
    const float* W_ih_f  = (const float*)d_in[4];
    const float* W_hh_f  = (const float*)d_in[5];
    const float* b_ih_f  = (const float*)d_in[6];
    const float* b_hh_f  = (const float*)d_in[7];
    const float* W_ih_b  = (const float*)d_in[8];
    const float* W_hh_b  = (const float*)d_in[9];
    const float* b_ih_b  = (const float*)d_in[10];
    const float* b_hh_b  = (const float*)d_in[11];
    const float* W_ih_d  = (const float*)d_in[12];
    const float* W_hh_d  = (const float*)d_in[13];
    const float* b_ih_d  = (const float*)d_in[14];
    const float* b_hh_d  = (const float*)d_in[15];
    const float* W_fc    = (const float*)d_in[16];
    const float* b_fc    = (const float*)d_in[17];
    float* out = (float*)d_out;

    const int SMEM = 2 * STG_BYTES;   // 112KB
    cudaFuncSetAttribute(gru_step_mma<H1>,
        cudaFuncAttributeMaxDynamicSharedMemorySize, SMEM);
    cudaFuncSetAttribute(gru_step_mma<H2>,
        cudaFuncAttributeMaxDynamicSharedMemorySize, SMEM);

    // prep (2 launches): proj tables, then weight limb-split + encoder h zero
    proj_all_kernel<<<dim3(3 * H2 / 64, 2, 3), 256>>>(
        enc_emb, dec_emb, W_ih_f, W_ih_b, W_ih_d, b_ih_f, b_ih_b, b_ih_d);
    {
        long long total = 2LL * NF + ND;
        split_all_kernel<<<(unsigned)((total + 255) / 256), 256>>>(W_hh_f, W_hh_b, W_hh_d);
    }

    for (int s = 0; s < S_; s++)
        gru_step_mma<H1><<<dim3(H1 / 32, B_ / 128, 2), 512, SMEM>>>(
            src, b_hh_f, b_hh_b, s & 1, s);
    // s=63: pp=1 -> writes buffer 0; final encoder state in buffer 0

    init_dec_kernel<<<(B_ * H2 + 255) / 256, 256>>>(tgt);

    for (int t = 0; t < T_ - 1; t++) {
        gru_step_mma<H2><<<dim3(H2 / 32, B_ / 128, 1), 512, SMEM>>>(
            (const int*)nullptr, b_hh_d, b_hh_d, t & 1, 0);
        logits_partial_kernel<<<dim3(B_ / 32, 8), 256>>>(W_fc, t & 1);
        logits_reduce_kernel<<<B_, V_>>>(b_fc, out, t);
    }
}